// round 9
// baseline (speedup 1.0000x reference)
#include <cuda_runtime.h>

// Aggre_81226421502275: y[n] = mean_k( relu(mailbox[n,k,:]@W1 + b1) @ W2 + b2 )
// N=500000, K=16, F_IN=7, F_HID=40, F_OUT=3. All fp32.
//
// Strategy:
//  - mean is linear => y = (sum_k relu(m_k@W1+b1)) @ W2 / K + b2  (layer-2 per node, not per msg)
//  - one thread per node; k-tile of 4 messages
//  - hidden dim as 20 f32x2 pairs; fma.rn.f32x2 (FFMA2) doubles fp32 FMA throughput
//  - W1/b1 as packed pairs in shared (broadcast LDS.64), W1 pair loads amortized over the k-tile
//  - relu via fmaxf (FMNMX, alu pipe) to keep the fma pipe for FFMA2

#define KK    16
#define FIN   7
#define FHID  40
#define FOUT  3
#define KT    4            // messages per k-tile
#define NT    (KK / KT)    // 4 tiles
#define JP    (FHID / 2)   // 20 hidden pairs
#define TPB   128

__device__ __forceinline__ unsigned long long bcast2(float x) {
    unsigned long long r;
    asm("mov.b64 %0, {%1, %1};" : "=l"(r) : "f"(x));
    return r;
}
__device__ __forceinline__ unsigned long long pack2(float x, float y) {
    unsigned long long r;
    asm("mov.b64 %0, {%1, %2};" : "=l"(r) : "f"(x), "f"(y));
    return r;
}
__device__ __forceinline__ void unpack2(unsigned long long v, float &x, float &y) {
    asm("mov.b64 {%0, %1}, %2;" : "=f"(x), "=f"(y) : "l"(v));
}
__device__ __forceinline__ unsigned long long fma2(unsigned long long a,
                                                   unsigned long long b,
                                                   unsigned long long c) {
    unsigned long long d;
    asm("fma.rn.f32x2 %0, %1, %2, %3;" : "=l"(d) : "l"(a), "l"(b), "l"(c));
    return d;
}

__global__ __launch_bounds__(TPB)
void aggre_mlp_kernel(const float* __restrict__ mailbox,
                      const float* __restrict__ W1,
                      const float* __restrict__ b1,
                      const float* __restrict__ W2,
                      const float* __restrict__ b2,
                      float* __restrict__ out,
                      int N)
{
    // Packed weights in shared memory (broadcast reads, conflict-free).
    __shared__ unsigned long long sW1p[FIN * JP];   // [f][jp] pair (2*jp, 2*jp+1)
    __shared__ unsigned long long sb1p[JP];
    __shared__ float              sW2[FHID * FOUT]; // row-major [j][o]
    __shared__ float              sb2[FOUT];

    const int tid = threadIdx.x;
    for (int i = tid; i < FIN * JP; i += TPB) sW1p[i] = pack2(W1[2 * i], W1[2 * i + 1]);
    for (int i = tid; i < JP;       i += TPB) sb1p[i] = pack2(b1[2 * i], b1[2 * i + 1]);
    for (int i = tid; i < FHID * FOUT; i += TPB) sW2[i] = W2[i];
    if (tid < FOUT) sb2[tid] = b2[tid];
    __syncthreads();

    const int n = blockIdx.x * TPB + tid;
    if (n >= N) return;

    float hsum[FHID];
#pragma unroll
    for (int j = 0; j < FHID; j++) hsum[j] = 0.0f;

    // 448 bytes per node, 16B-aligned: 28 float4 = 4 tiles x 7 float4.
    const float4* mp = reinterpret_cast<const float4*>(mailbox + (long long)n * (KK * FIN));

#pragma unroll 1
    for (int t = 0; t < NT; t++) {
        // Load one k-tile (4 messages x 7 feats = 28 floats) and broadcast-pack.
        unsigned long long mb[KT * FIN];
#pragma unroll
        for (int i = 0; i < (KT * FIN) / 4; i++) {
            float4 vv = mp[t * ((KT * FIN) / 4) + i];
            mb[i * 4 + 0] = bcast2(vv.x);
            mb[i * 4 + 1] = bcast2(vv.y);
            mb[i * 4 + 2] = bcast2(vv.z);
            mb[i * 4 + 3] = bcast2(vv.w);
        }

#pragma unroll
        for (int jp = 0; jp < JP; jp++) {
            unsigned long long w[FIN];
#pragma unroll
            for (int f = 0; f < FIN; f++) w[f] = sW1p[f * JP + jp];
            const unsigned long long bb = sb1p[jp];

#pragma unroll
            for (int kk = 0; kk < KT; kk++) {
                unsigned long long acc = bb;
#pragma unroll
                for (int f = 0; f < FIN; f++)
                    acc = fma2(mb[kk * FIN + f], w[f], acc);
                float ax, ay;
                unpack2(acc, ax, ay);
                hsum[2 * jp]     += fmaxf(ax, 0.0f);
                hsum[2 * jp + 1] += fmaxf(ay, 0.0f);
            }
        }
    }

    // Layer 2 on the k-summed hidden vector: y = hsum @ W2 / K + b2.
    float y0 = 0.0f, y1 = 0.0f, y2 = 0.0f;
#pragma unroll
    for (int j = 0; j < FHID; j++) {
        const float h = hsum[j];
        y0 = fmaf(h, sW2[j * FOUT + 0], y0);
        y1 = fmaf(h, sW2[j * FOUT + 1], y1);
        y2 = fmaf(h, sW2[j * FOUT + 2], y2);
    }
    const float inv = 1.0f / (float)KK;
    out[n * FOUT + 0] = fmaf(y0, inv, sb2[0]);
    out[n * FOUT + 1] = fmaf(y1, inv, sb2[1]);
    out[n * FOUT + 2] = fmaf(y2, inv, sb2[2]);
}

extern "C" void kernel_launch(void* const* d_in, const int* in_sizes, int n_in,
                              void* d_out, int out_size)
{
    const float* mailbox = (const float*)d_in[0];
    const float* W1      = (const float*)d_in[1];
    const float* b1      = (const float*)d_in[2];
    const float* W2      = (const float*)d_in[3];
    const float* b2      = (const float*)d_in[4];
    float*       out     = (float*)d_out;

    const int N = in_sizes[0] / (KK * FIN);
    const int blocks = (N + TPB - 1) / TPB;
    aggre_mlp_kernel<<<blocks, TPB>>>(mailbox, W1, b1, W2, b2, out, N);
}